// round 5
// baseline (speedup 1.0000x reference)
#include <cuda_runtime.h>

#define Bsz 128
#define Tsz 512
#define Isz 64
#define Hsz 256
#define Gsz 768   // 3*H

// ---- device scratch (no cudaMalloc allowed) --------------------------------
__device__ float    g_gx  [(size_t)Tsz * Bsz * Gsz];  // [t][b][768] gate preactivations
__device__ float    g_h1  [(size_t)Tsz * Bsz * Hsz];  // [t][b][256] layer-0 outputs
__device__ float    g_hbuf[2 * Bsz * Hsz];            // double-buffered hidden state
__device__ unsigned g_cnt [2 * Tsz * 8];              // per layer/step/batch-group barrier

#define SCAN_SMEM_FLOATS (3*16*256 + 16*260 + 16*48)
#define SCAN_SMEM_BYTES  (SCAN_SMEM_FLOATS * 4)       // 68864 B

// ---- zero hidden state (+ optionally barrier counters) ---------------------
__global__ void zero_state(int zero_cnt) {
    const int stride = gridDim.x * blockDim.x;
    const int i0 = blockIdx.x * blockDim.x + threadIdx.x;
    for (int i = i0; i < 2 * Bsz * Hsz; i += stride) g_hbuf[i] = 0.0f;
    if (zero_cnt)
        for (int i = i0; i < 2 * Tsz * 8; i += stride) g_cnt[i] = 0u;
}

// ---- SGEMM (NT): g_gx[m][n] = sum_k Arow(m)[k]*W[n][k] + bias[n] ------------
// mode 0: Arow(m)=x[(b*T+t)*I], m = t*128+b (bm=t,rowA=b), K=64
// mode 1: Arow(m)=g_h1+m*256, K=256.  Tile 128x128xBK8, 256 thr, 8x8 micro.
__global__ __launch_bounds__(256) void sgemm_nt(
    const float* __restrict__ A, const float* __restrict__ W,
    const float* __restrict__ bias, int K, int mode)
{
    __shared__ float As[8][128];
    __shared__ float Ws[8][128];

    const int tid = threadIdx.x;
    const int tx = tid & 15, ty = tid >> 4;
    const int bm = blockIdx.y, bn = blockIdx.x;
    const int rowA = tid >> 1;
    const int kq = (tid & 1) * 4;

    const float* aptr;
    if (mode == 0) aptr = A    + ((size_t)rowA * Tsz + bm) * Isz;
    else           aptr = g_h1 + ((size_t)bm * 128 + rowA) * Hsz;
    const float* wptr = W + ((size_t)bn * 128 + rowA) * K;

    float acc[8][8];
#pragma unroll
    for (int i = 0; i < 8; ++i)
#pragma unroll
        for (int j = 0; j < 8; ++j) acc[i][j] = 0.0f;

    for (int k0 = 0; k0 < K; k0 += 8) {
        const float4 av = *(const float4*)(aptr + k0 + kq);
        const float4 wv = *(const float4*)(wptr + k0 + kq);
        __syncthreads();
        As[kq+0][rowA] = av.x; As[kq+1][rowA] = av.y;
        As[kq+2][rowA] = av.z; As[kq+3][rowA] = av.w;
        Ws[kq+0][rowA] = wv.x; Ws[kq+1][rowA] = wv.y;
        Ws[kq+2][rowA] = wv.z; Ws[kq+3][rowA] = wv.w;
        __syncthreads();
#pragma unroll
        for (int kk = 0; kk < 8; ++kk) {
            float a[8], w[8];
            *(float4*)&a[0] = *(const float4*)&As[kk][ty*4];
            *(float4*)&a[4] = *(const float4*)&As[kk][64 + ty*4];
            *(float4*)&w[0] = *(const float4*)&Ws[kk][tx*4];
            *(float4*)&w[4] = *(const float4*)&Ws[kk][64 + tx*4];
#pragma unroll
            for (int i = 0; i < 8; ++i)
#pragma unroll
                for (int j = 0; j < 8; ++j)
                    acc[i][j] = fmaf(a[i], w[j], acc[i][j]);
        }
    }

    const float4 bv0 = *(const float4*)(bias + bn*128 + tx*4);
    const float4 bv1 = *(const float4*)(bias + bn*128 + 64 + tx*4);
#pragma unroll
    for (int i = 0; i < 8; ++i) {
        const int mloc = (i < 4) ? (ty*4 + i) : (64 + ty*4 + i - 4);
        float* c = g_gx + ((size_t)bm*128 + mloc) * Gsz + bn*128;
        float4 v0 = make_float4(acc[i][0]+bv0.x, acc[i][1]+bv0.y,
                                acc[i][2]+bv0.z, acc[i][3]+bv0.w);
        float4 v1 = make_float4(acc[i][4]+bv1.x, acc[i][5]+bv1.y,
                                acc[i][6]+bv1.z, acc[i][7]+bv1.w);
        *(float4*)(c + tx*4)      = v0;
        *(float4*)(c + 64 + tx*4) = v1;
    }
}

// ---- persistent GRU scan: 128 CTAs (8 bg x 16 hg), 16b x 16j tile each -----
__global__ __launch_bounds__(256, 1) void gru_scan(
    const float* __restrict__ Whh, const float* __restrict__ bhh,
    int layer, int write_ys)
{
    extern __shared__ float sm[];
    float* sw  = sm;                    // [48][256] weights (row = g*16+u)
    float* sh  = sm + 3*16*256;         // [16][260] current h (padded)
    float* sgx = sh + 16*260;           // [16][48]  gx stage

    const int tid = threadIdx.x;
    const int bg  = blockIdx.x >> 4;    // 0..7
    const int hg  = blockIdx.x & 15;    // 0..15
    const int b0  = bg << 4, j0 = hg << 4;
    const int bl  = tid & 15, jl = tid >> 4;
    const int b   = b0 + bl,  j  = j0 + jl;

    // weight tile -> smem, once (48 rows x 64 float4)
    for (int idx = tid; idx < 3072; idx += 256) {
        const int row = idx >> 6, k4 = idx & 63;
        const int g = row >> 4,  u  = row & 15;
        ((float4*)sw)[idx] =
            __ldg((const float4*)(Whh + (size_t)((g << 8) + j0 + u) * 256) + k4);
    }
    const float bhr = bhh[j];
    const float bhz = bhh[256 + j];
    const float bhn = bhh[512 + j];
    unsigned* cnt = g_cnt + layer * (Tsz * 8);

    int cur = 0;
    for (int t = 0; t < Tsz; ++t) {
        // stage h tile (L2 path; L1 stale across SMs)
        {
            const float* hsrc = g_hbuf + cur * (Bsz * Hsz) + (b0 << 8);
#pragma unroll
            for (int r = 0; r < 4; ++r) {
                const int i = tid + (r << 8);
                const int bb = i >> 6, k4 = i & 63;
                float4 v = __ldcg((const float4*)(hsrc + (bb << 8)) + k4);
                *(float4*)(sh + bb * 260 + (k4 << 2)) = v;
            }
        }
        // stage gx tile: 16 b x 3 gates x 16 floats
        if (tid < 192) {
            const int seg = tid >> 2, q = tid & 3;
            const int bb = seg / 3, g = seg - bb * 3;
            float4 v = *(const float4*)(g_gx + (size_t)((t << 7) + b0 + bb) * Gsz
                                        + (g << 8) + j0 + (q << 2));
            *(float4*)(sgx + bb * 48 + (g << 4) + (q << 2)) = v;
        }
        __syncthreads();

        float accr = sgx[bl*48 + jl]      + bhr;
        float accz = sgx[bl*48 + 16 + jl] + bhz;
        const float gxn = sgx[bl*48 + 32 + jl];
        float accn = bhn;

        const float4* hv = (const float4*)(sh + bl * 260);
        const float4* wr = (const float4*)(sw + (jl << 8));
        const float4* wz = (const float4*)(sw + ((16 + jl) << 8));
        const float4* wn = (const float4*)(sw + ((32 + jl) << 8));
#pragma unroll 8
        for (int k4 = 0; k4 < 64; ++k4) {
            const float4 h4 = hv[k4];
            const float4 w0 = wr[k4], w1 = wz[k4], w2 = wn[k4];
            accr = fmaf(h4.x, w0.x, accr); accr = fmaf(h4.y, w0.y, accr);
            accr = fmaf(h4.z, w0.z, accr); accr = fmaf(h4.w, w0.w, accr);
            accz = fmaf(h4.x, w1.x, accz); accz = fmaf(h4.y, w1.y, accz);
            accz = fmaf(h4.z, w1.z, accz); accz = fmaf(h4.w, w1.w, accz);
            accn = fmaf(h4.x, w2.x, accn); accn = fmaf(h4.y, w2.y, accn);
            accn = fmaf(h4.z, w2.z, accn); accn = fmaf(h4.w, w2.w, accn);
        }

        const float r = 1.0f / (1.0f + __expf(-accr));
        const float z = 1.0f / (1.0f + __expf(-accz));
        const float n = tanhf(fmaf(r, accn, gxn));
        const float hold = sh[bl * 260 + j0 + jl];
        const float hnew = fmaf(z, hold - n, n);   // (1-z)*n + z*h

        __stcg(g_hbuf + (cur ^ 1) * (Bsz * Hsz) + (b << 8) + j, hnew);
        if (write_ys)
            g_h1[(size_t)((t << 7) + b) * Hsz + j] = hnew;

        __threadfence();
        __syncthreads();
        if (tid == 0) {
            unsigned* c = cnt + (t << 3) + bg;
            atomicAdd(c, 1u);
            while (*(volatile unsigned*)c < 16u) { }
            __threadfence();
        }
        __syncthreads();
        cur ^= 1;
    }
}

// ---- head: out[b] = W2 . relu(W1 . h_last[b] + b1) + b2 --------------------
__global__ void head_kernel(const float* __restrict__ W1, const float* __restrict__ b1,
                            const float* __restrict__ W2, const float* __restrict__ b2,
                            float* __restrict__ out)
{
    __shared__ float red[128];
    const int b = blockIdx.x, u = threadIdx.x;
    const float* hb = g_hbuf + (b << 8);    // final h in buffer 0 (T even)
    const float* w  = W1 + (size_t)u * 256;

    float acc = b1[u];
#pragma unroll 8
    for (int k4 = 0; k4 < 64; ++k4) {
        const float4 h4 = *(const float4*)(hb + (k4 << 2));
        const float4 w4 = __ldg((const float4*)w + k4);
        acc = fmaf(h4.x, w4.x, acc); acc = fmaf(h4.y, w4.y, acc);
        acc = fmaf(h4.z, w4.z, acc); acc = fmaf(h4.w, w4.w, acc);
    }
    red[u] = fmaxf(acc, 0.0f) * __ldg(W2 + u);
    __syncthreads();
#pragma unroll
    for (int s = 64; s > 0; s >>= 1) {
        if (u < s) red[u] += red[u + s];
        __syncthreads();
    }
    if (u == 0) out[b] = red[0] + b2[0];
}

// ---- launch sequence (graph-capturable: kernel launches only) --------------
extern "C" void kernel_launch(void* const* d_in, const int* in_sizes, int n_in,
                              void* d_out, int out_size)
{
    const float* x    = (const float*)d_in[0];
    const float* Wih0 = (const float*)d_in[1];
    const float* Whh0 = (const float*)d_in[2];
    const float* bih0 = (const float*)d_in[3];
    const float* bhh0 = (const float*)d_in[4];
    const float* Wih1 = (const float*)d_in[5];
    const float* Whh1 = (const float*)d_in[6];
    const float* bih1 = (const float*)d_in[7];
    const float* bhh1 = (const float*)d_in[8];
    const float* W1   = (const float*)d_in[9];
    const float* b1   = (const float*)d_in[10];
    const float* W2   = (const float*)d_in[11];
    const float* b2   = (const float*)d_in[12];
    float* out = (float*)d_out;

    cudaFuncSetAttribute(gru_scan, cudaFuncAttributeMaxDynamicSharedMemorySize,
                         SCAN_SMEM_BYTES);

    const dim3 ggrid(6, 512);

    // fresh state + barrier counters every replay
    zero_state<<<64, 256>>>(1);

    // layer 0
    sgemm_nt<<<ggrid, 256>>>(x, Wih0, bih0, Isz, 0);
    gru_scan<<<128, 256, SCAN_SMEM_BYTES>>>(Whh0, bhh0, 0, 1);

    // layer 1 (re-zero hidden state: layer 1 starts from h=0)
    sgemm_nt<<<ggrid, 256>>>(x, Wih1, bih1, Hsz, 1);
    zero_state<<<64, 256>>>(0);
    gru_scan<<<128, 256, SCAN_SMEM_BYTES>>>(Whh1, bhh1, 1, 0);

    // head
    head_kernel<<<128, 128>>>(W1, b1, W2, b2, out);
}

// round 6
// speedup vs baseline: 1.0768x; 1.0768x over previous
#include <cuda_runtime.h>

#define Bsz 128
#define Tsz 512
#define Isz 64
#define Hsz 256
#define Gsz 768   // 3*H

// ---- device scratch (no cudaMalloc allowed) --------------------------------
__device__ float    g_gx  [(size_t)Tsz * Bsz * Gsz];  // [t][b][768] gate preactivations
__device__ float    g_h1  [(size_t)Tsz * Bsz * Hsz];  // [t][b][256] layer-0 outputs
__device__ float    g_hbuf[2 * Bsz * Hsz];            // double-buffered hidden state
__device__ unsigned g_cnt [2 * Tsz * 8];              // per layer/step/batch-group barrier

// smem: weights 48 rows x 260 (padded), h 16 x 260 (padded), gx stage 16 x 48
#define SW_STRIDE 260
#define SCAN_SMEM_FLOATS (48*SW_STRIDE + 16*260 + 16*48)
#define SCAN_SMEM_BYTES  (SCAN_SMEM_FLOATS * 4)   // 69632 B

// ---- zero hidden state (+ optionally barrier counters) ---------------------
__global__ void zero_state(int zero_cnt) {
    const int stride = gridDim.x * blockDim.x;
    const int i0 = blockIdx.x * blockDim.x + threadIdx.x;
    for (int i = i0; i < 2 * Bsz * Hsz; i += stride) g_hbuf[i] = 0.0f;
    if (zero_cnt)
        for (int i = i0; i < 2 * Tsz * 8; i += stride) g_cnt[i] = 0u;
}

// ---- SGEMM (NT): g_gx[m][n] = sum_k Arow(m)[k]*W[n][k] + bias[n] ------------
// mode 0: Arow(m)=x[(b*T+t)*I], m = t*128+b (bm=t,rowA=b), K=64
// mode 1: Arow(m)=g_h1+m*256, K=256.  Tile 128x128xBK8, 256 thr, 8x8 micro.
__global__ __launch_bounds__(256) void sgemm_nt(
    const float* __restrict__ A, const float* __restrict__ W,
    const float* __restrict__ bias, int K, int mode)
{
    __shared__ float As[8][128];
    __shared__ float Ws[8][128];

    const int tid = threadIdx.x;
    const int tx = tid & 15, ty = tid >> 4;
    const int bm = blockIdx.y, bn = blockIdx.x;
    const int rowA = tid >> 1;
    const int kq = (tid & 1) * 4;

    const float* aptr;
    if (mode == 0) aptr = A    + ((size_t)rowA * Tsz + bm) * Isz;
    else           aptr = g_h1 + ((size_t)bm * 128 + rowA) * Hsz;
    const float* wptr = W + ((size_t)bn * 128 + rowA) * K;

    float acc[8][8];
#pragma unroll
    for (int i = 0; i < 8; ++i)
#pragma unroll
        for (int j = 0; j < 8; ++j) acc[i][j] = 0.0f;

    for (int k0 = 0; k0 < K; k0 += 8) {
        const float4 av = *(const float4*)(aptr + k0 + kq);
        const float4 wv = *(const float4*)(wptr + k0 + kq);
        __syncthreads();
        As[kq+0][rowA] = av.x; As[kq+1][rowA] = av.y;
        As[kq+2][rowA] = av.z; As[kq+3][rowA] = av.w;
        Ws[kq+0][rowA] = wv.x; Ws[kq+1][rowA] = wv.y;
        Ws[kq+2][rowA] = wv.z; Ws[kq+3][rowA] = wv.w;
        __syncthreads();
#pragma unroll
        for (int kk = 0; kk < 8; ++kk) {
            float a[8], w[8];
            *(float4*)&a[0] = *(const float4*)&As[kk][ty*4];
            *(float4*)&a[4] = *(const float4*)&As[kk][64 + ty*4];
            *(float4*)&w[0] = *(const float4*)&Ws[kk][tx*4];
            *(float4*)&w[4] = *(const float4*)&Ws[kk][64 + tx*4];
#pragma unroll
            for (int i = 0; i < 8; ++i)
#pragma unroll
                for (int j = 0; j < 8; ++j)
                    acc[i][j] = fmaf(a[i], w[j], acc[i][j]);
        }
    }

    const float4 bv0 = *(const float4*)(bias + bn*128 + tx*4);
    const float4 bv1 = *(const float4*)(bias + bn*128 + 64 + tx*4);
#pragma unroll
    for (int i = 0; i < 8; ++i) {
        const int mloc = (i < 4) ? (ty*4 + i) : (64 + ty*4 + i - 4);
        float* c = g_gx + ((size_t)bm*128 + mloc) * Gsz + bn*128;
        float4 v0 = make_float4(acc[i][0]+bv0.x, acc[i][1]+bv0.y,
                                acc[i][2]+bv0.z, acc[i][3]+bv0.w);
        float4 v1 = make_float4(acc[i][4]+bv1.x, acc[i][5]+bv1.y,
                                acc[i][6]+bv1.z, acc[i][7]+bv1.w);
        *(float4*)(c + tx*4)      = v0;
        *(float4*)(c + 64 + tx*4) = v1;
    }
}

// ---- persistent GRU scan: 128 CTAs (8 bg x 16 hg), 16b x 16j tile each -----
// Pipelined: gx(t+1) prefetched to regs during compute of t; release/acquire
// barrier (red.release + ld.acquire poll) instead of fences+atomicAdd.
__global__ __launch_bounds__(256, 1) void gru_scan(
    const float* __restrict__ Whh, const float* __restrict__ bhh,
    int layer, int write_ys)
{
    extern __shared__ float sm[];
    float* sw  = sm;                         // [48][SW_STRIDE]
    float* sh  = sm + 48 * SW_STRIDE;        // [16][260]
    float* sgx = sh + 16 * 260;              // [16][48]

    const int tid = threadIdx.x;
    const int bg  = blockIdx.x >> 4;         // 0..7
    const int hg  = blockIdx.x & 15;         // 0..15
    const int b0  = bg << 4, j0 = hg << 4;
    const int bl  = tid & 15, jl = tid >> 4;
    const int b   = b0 + bl,  j  = j0 + jl;

    // weight tile -> smem, once (48 rows x 64 float4), padded rows
    for (int idx = tid; idx < 3072; idx += 256) {
        const int row = idx >> 6, k4 = idx & 63;
        const int g = row >> 4,  u  = row & 15;
        *(float4*)(sw + row * SW_STRIDE + (k4 << 2)) =
            __ldg((const float4*)(Whh + (size_t)((g << 8) + j0 + u) * 256) + k4);
    }
    const float bhr = bhh[j];
    const float bhz = bhh[256 + j];
    const float bhn = bhh[512 + j];
    unsigned* cnt = g_cnt + layer * (Tsz * 8);

    // gx staging thread role (192 threads, one float4 each)
    const bool gxth = tid < 192;
    const int  seg  = tid >> 2, q = tid & 3;
    const int  gbb  = seg / 3, gg = seg - gbb * 3;
    const float* gxp = g_gx + (size_t)(b0 + gbb) * Gsz + (gg << 8) + j0 + (q << 2);
    const size_t gxstep = (size_t)128 * Gsz;

    float4 gxa = make_float4(0.f, 0.f, 0.f, 0.f);
    if (gxth) gxa = __ldg((const float4*)gxp);   // t = 0

    int cur = 0;
    for (int t = 0; t < Tsz; ++t) {
        // 1) issue h loads early (L2 path; L1 stale across SMs)
        float4 hr[4];
        {
            const float* hsrc = g_hbuf + cur * (Bsz * Hsz) + (b0 << 8);
#pragma unroll
            for (int r = 0; r < 4; ++r) {
                const int i = tid + (r << 8);
                hr[r] = __ldcg((const float4*)(hsrc + ((i >> 6) << 8)) + (i & 63));
            }
        }
        // 2) stage prefetched gx(t) into smem; kick off gx(t+1) prefetch
        if (gxth) {
            *(float4*)(sgx + gbb * 48 + (gg << 4) + (q << 2)) = gxa;
            if (t + 1 < Tsz)
                gxa = __ldcg((const float4*)(gxp + (size_t)(t + 1) * gxstep));
        }
        // 3) land h into smem
#pragma unroll
        for (int r = 0; r < 4; ++r) {
            const int i = tid + (r << 8);
            *(float4*)(sh + (i >> 6) * 260 + ((i & 63) << 2)) = hr[r];
        }
        __syncthreads();

        float accr = sgx[bl*48 + jl]      + bhr;
        float accz = sgx[bl*48 + 16 + jl] + bhz;
        const float gxn = sgx[bl*48 + 32 + jl];
        float accn = bhn;

        const float4* hv = (const float4*)(sh + bl * 260);
        const float4* wr = (const float4*)(sw + (jl)      * SW_STRIDE);
        const float4* wz = (const float4*)(sw + (16 + jl) * SW_STRIDE);
        const float4* wn = (const float4*)(sw + (32 + jl) * SW_STRIDE);
#pragma unroll 8
        for (int k4 = 0; k4 < 64; ++k4) {
            const float4 h4 = hv[k4];
            const float4 w0 = wr[k4], w1 = wz[k4], w2 = wn[k4];
            accr = fmaf(h4.x, w0.x, accr); accr = fmaf(h4.y, w0.y, accr);
            accr = fmaf(h4.z, w0.z, accr); accr = fmaf(h4.w, w0.w, accr);
            accz = fmaf(h4.x, w1.x, accz); accz = fmaf(h4.y, w1.y, accz);
            accz = fmaf(h4.z, w1.z, accz); accz = fmaf(h4.w, w1.w, accz);
            accn = fmaf(h4.x, w2.x, accn); accn = fmaf(h4.y, w2.y, accn);
            accn = fmaf(h4.z, w2.z, accn); accn = fmaf(h4.w, w2.w, accn);
        }

        const float r = 1.0f / (1.0f + __expf(-accr));
        const float z = 1.0f / (1.0f + __expf(-accz));
        const float n = tanhf(fmaf(r, accn, gxn));
        const float hold = sh[bl * 260 + j0 + jl];
        const float hnew = fmaf(z, hold - n, n);   // (1-z)*n + z*h

        __stcg(g_hbuf + (cur ^ 1) * (Bsz * Hsz) + (b << 8) + j, hnew);
        if (write_ys)
            g_h1[(size_t)((t << 7) + b) * Hsz + j] = hnew;

        __syncthreads();   // all stores of this CTA issued before arrive
        if (tid == 0) {
            unsigned* c = cnt + (t << 3) + bg;
            // release-arrive: orders all prior (sync'ed) stores, no return trip
            asm volatile("red.release.gpu.global.add.u32 [%0], 1;"
                         :: "l"(c) : "memory");
            unsigned v;
            do {
                asm volatile("ld.acquire.gpu.global.u32 %0, [%1];"
                             : "=r"(v) : "l"(c) : "memory");
            } while (v < 16u);
        }
        __syncthreads();
        cur ^= 1;
    }
}

// ---- head: out[b] = W2 . relu(W1 . h_last[b] + b1) + b2 --------------------
__global__ void head_kernel(const float* __restrict__ W1, const float* __restrict__ b1,
                            const float* __restrict__ W2, const float* __restrict__ b2,
                            float* __restrict__ out)
{
    __shared__ float red[128];
    const int b = blockIdx.x, u = threadIdx.x;
    const float* hb = g_hbuf + (b << 8);    // final h in buffer 0 (T even)
    const float* w  = W1 + (size_t)u * 256;

    float acc = b1[u];
#pragma unroll 8
    for (int k4 = 0; k4 < 64; ++k4) {
        const float4 h4 = __ldcg((const float4*)hb + k4);
        const float4 w4 = __ldg((const float4*)w + k4);
        acc = fmaf(h4.x, w4.x, acc); acc = fmaf(h4.y, w4.y, acc);
        acc = fmaf(h4.z, w4.z, acc); acc = fmaf(h4.w, w4.w, acc);
    }
    red[u] = fmaxf(acc, 0.0f) * __ldg(W2 + u);
    __syncthreads();
#pragma unroll
    for (int s = 64; s > 0; s >>= 1) {
        if (u < s) red[u] += red[u + s];
        __syncthreads();
    }
    if (u == 0) out[b] = red[0] + b2[0];
}

// ---- launch sequence (graph-capturable: kernel launches only) --------------
extern "C" void kernel_launch(void* const* d_in, const int* in_sizes, int n_in,
                              void* d_out, int out_size)
{
    const float* x    = (const float*)d_in[0];
    const float* Wih0 = (const float*)d_in[1];
    const float* Whh0 = (const float*)d_in[2];
    const float* bih0 = (const float*)d_in[3];
    const float* bhh0 = (const float*)d_in[4];
    const float* Wih1 = (const float*)d_in[5];
    const float* Whh1 = (const float*)d_in[6];
    const float* bih1 = (const float*)d_in[7];
    const float* bhh1 = (const float*)d_in[8];
    const float* W1   = (const float*)d_in[9];
    const float* b1   = (const float*)d_in[10];
    const float* W2   = (const float*)d_in[11];
    const float* b2   = (const float*)d_in[12];
    float* out = (float*)d_out;

    cudaFuncSetAttribute(gru_scan, cudaFuncAttributeMaxDynamicSharedMemorySize,
                         SCAN_SMEM_BYTES);

    const dim3 ggrid(6, 512);

    // fresh state + barrier counters every replay
    zero_state<<<64, 256>>>(1);

    // layer 0
    sgemm_nt<<<ggrid, 256>>>(x, Wih0, bih0, Isz, 0);
    gru_scan<<<128, 256, SCAN_SMEM_BYTES>>>(Whh0, bhh0, 0, 1);

    // layer 1 (re-zero hidden state: layer 1 starts from h=0)
    sgemm_nt<<<ggrid, 256>>>(x, Wih1, bih1, Hsz, 1);
    zero_state<<<64, 256>>>(0);
    gru_scan<<<128, 256, SCAN_SMEM_BYTES>>>(Whh1, bhh1, 1, 0);

    // head
    head_kernel<<<128, 128>>>(W1, b1, W2, b2, out);
}